// round 1
// baseline (speedup 1.0000x reference)
#include <cuda_runtime.h>
#include <cuda_bf16.h>

// DeformableConvLayer: B=4, H=W=256, C=64, K=3x3, UNITS=1, G=1.
// Inputs (metadata order): input_fp [4,256,256,64] f32, gt_mask [1,256,256,1] f32,
// offset [4,256,256,18] f32, kernel [3,3,64,1] f32, bias [1] f32.
// Output: [4,256,256,1] f32 (262144 floats).
//
// Strategy: one warp per output pixel.
//   lanes 0..8  : compute the 9 tap coordinates (exact reference semantics:
//                 padded-index-grid base taps, mask compare at padded coords,
//                 offset gated by mask-diff, floor+clip, padded-input sample)
//   all lanes   : for each tap, gather float2 (2 channels/lane -> 256B coalesced)
//                 and FMA against register-resident kernel weights
//   warp-reduce : 5x shfl_xor, lane 0 writes out + bias.

namespace {

constexpr int Hc = 256;
constexpr int Wc = 256;
constexpr int Cc = 64;
constexpr int PIX_TOTAL = 4 * Hc * Wc;          // 262144
constexpr int WARPS_PER_BLOCK = 8;
constexpr int THREADS = WARPS_PER_BLOCK * 32;   // 256
constexpr int BLOCKS = PIX_TOTAL / WARPS_PER_BLOCK;

__global__ __launch_bounds__(THREADS)
void dcn_warp_per_pixel(const float* __restrict__ input,
                        const float* __restrict__ mask,     // [256,256]
                        const float* __restrict__ offset,   // [pix,18]
                        const float* __restrict__ kern,     // [9,64]
                        const float* __restrict__ bias,
                        float* __restrict__ out)
{
    const unsigned FULL = 0xffffffffu;
    const int lane = threadIdx.x & 31;
    const int pix  = blockIdx.x * WARPS_PER_BLOCK + (threadIdx.x >> 5);

    const int b = pix >> 16;
    const int h = (pix >> 8) & 255;
    const int w = pix & 255;

    // Per-lane kernel weights: tap k, channels {2*lane, 2*lane+1}. Hot in L1.
    float2 wk[9];
#pragma unroll
    for (int k = 0; k < 9; k++)
        wk[k] = *reinterpret_cast<const float2*>(kern + k * Cc + 2 * lane);

    // Load 18 offset floats across lanes 0..17, distribute via shuffle.
    float offv = 0.0f;
    if (lane < 18) offv = offset[(size_t)pix * 18 + lane];
    const float y_off = __shfl_sync(FULL, offv, (2 * lane) & 31);
    const float x_off = __shfl_sync(FULL, offv, (2 * lane + 1) & 31);

    // Lanes 0..8: compute packed gather index for tap `lane`.
    // packed = ((y0-1)<<8)|(x0-1) into the UNPADDED input, or -1 for a zero (pad) sample.
    int packed = -1;
    if (lane < 9) {
        const int ky = lane / 3;
        const int kx = lane - ky * 3;
        const int yb = h + ky - 1;
        const int xb = w + kx - 1;
        // Joint in-bounds: padded 2D index grid zeroes BOTH coords at any border.
        const bool inb = (yb >= 0) & (yb < Hc) & (xb >= 0) & (xb < Wc);
        const int yi = inb ? yb : 0;
        const int xi = inb ? xb : 0;

        // p_mask = padded_mask[yi, xi]  (pad row/col 0 -> 0)
        const float p_mask = (yi >= 1 && xi >= 1) ? mask[(yi - 1) * Wc + (xi - 1)] : 0.0f;

        // Offset sample point in padded coords, floor then clip to [0, 257].
        int yo = (int)floorf((float)yi + y_off);
        int xo = (int)floorf((float)xi + x_off);
        yo = min(max(yo, 0), Hc + 1);
        xo = min(max(xo, 0), Wc + 1);
        const float p_mask_off = (yo >= 1 && yo <= Hc && xo >= 1 && xo <= Wc)
                                     ? mask[(yo - 1) * Wc + (xo - 1)] : 0.0f;

        const float diff = (p_mask != p_mask_off) ? 1.0f : 0.0f;

        const float yf = fminf(fmaxf((float)yi + y_off * diff, 0.0f), (float)(Hc - 1));
        const float xf = fminf(fmaxf((float)xi + x_off * diff, 0.0f), (float)(Wc - 1));
        const int y0 = (int)floorf(yf);
        const int x0 = (int)floorf(xf);

        // Sample padded input fp[y0, x0]: zero when y0==0 || x0==0, else input[y0-1, x0-1].
        if (y0 >= 1 && x0 >= 1)
            packed = ((y0 - 1) << 8) | (x0 - 1);
    }

    const float* inp = input + (size_t)b * (Hc * Wc * Cc) + 2 * lane;

    float acc = 0.0f;
#pragma unroll
    for (int k = 0; k < 9; k++) {
        const int p = __shfl_sync(FULL, packed, k);   // uniform across warp
        if (p >= 0) {
            const float2 v = *reinterpret_cast<const float2*>(inp + (size_t)p * Cc);
            acc = fmaf(v.x, wk[k].x, acc);
            acc = fmaf(v.y, wk[k].y, acc);
        }
    }

    // Warp reduction.
#pragma unroll
    for (int s = 16; s; s >>= 1)
        acc += __shfl_xor_sync(FULL, acc, s);

    if (lane == 0)
        out[pix] = acc + bias[0];
}

} // namespace

extern "C" void kernel_launch(void* const* d_in, const int* in_sizes, int n_in,
                              void* d_out, int out_size)
{
    const float* input  = (const float*)d_in[0];   // [4,256,256,64]
    const float* mask   = (const float*)d_in[1];   // [1,256,256,1]
    const float* offset = (const float*)d_in[2];   // [4,256,256,18]
    const float* kern   = (const float*)d_in[3];   // [3,3,64,1]
    const float* bias   = (const float*)d_in[4];   // [1]
    float* out = (float*)d_out;                    // [4,256,256,1]

    dcn_warp_per_pixel<<<BLOCKS, THREADS>>>(input, mask, offset, kern, bias, out);
}